// round 1
// baseline (speedup 1.0000x reference)
#include <cuda_runtime.h>
#include <stdint.h>

#define HH 256
#define WW 256
#define NPIX (HH*WW)

// ---------------- scratch (device globals; no allocations allowed) -------------
__device__ float          g_fb[NPIX];       // binomial-filtered f (float)
__device__ unsigned char  g_fq[NPIX];       // quantized f
__device__ unsigned char  g_gq[NPIX];       // quantized g
__device__ float          g_dfx[NPIX];      // x-gradient of fb
__device__ float          g_dfy[NPIX];      // y-gradient of fb
__device__ float          g_flow1[2*NPIX];  // vector + subpixel
__device__ float          g_flow2[2*NPIX];  // after median

// spiral rank of displacement s = (dj+3)*7 + (di+3), center-out spiral
__constant__ int c_spiral[49] = {
    42,43,44,45,46,47,48,
    41,20,21,22,23,24,25,
    40,19, 6, 7, 8, 9,26,
    39,18, 5, 0, 1,10,27,
    38,17, 4, 3, 2,11,28,
    37,16,15,14,13,12,29,
    36,35,34,33,32,31,30
};

// ---------------- helpers ----------------
__device__ __forceinline__ float imload(const float* __restrict__ img, int y, int x) {
    y = min(max(y, 0), HH - 1);
    x = min(max(x, 0), WW - 1);
    return img[y * WW + x];
}

// binomial [1 2 1]/4 vertical then horizontal, replicate padding —
// same op order / rounding as the reference
__device__ __forceinline__ float binom_at(const float* __restrict__ img, int y, int x) {
    float vL = (imload(img, y - 1, x - 1) + 2.0f * imload(img, y, x - 1) + imload(img, y + 1, x - 1)) * 0.25f;
    float vC = (imload(img, y - 1, x    ) + 2.0f * imload(img, y, x    ) + imload(img, y + 1, x    )) * 0.25f;
    float vR = (imload(img, y - 1, x + 1) + 2.0f * imload(img, y, x + 1) + imload(img, y + 1, x + 1)) * 0.25f;
    return (vL + 2.0f * vC + vR) * 0.25f;
}

__device__ __forceinline__ unsigned char quant(float v) {
    float r = rintf(v * 255.0f);          // round half-to-even, matches jnp.round
    r = fminf(fmaxf(r, 0.0f), 255.0f);
    return (unsigned char)r;
}

// ---------------- kernel 1: binomial + quantize + gradient ----------------
__global__ __launch_bounds__(256) void prep_kernel(const float* __restrict__ f,
                                                   const float* __restrict__ g) {
    __shared__ float sfb[18][18];
    int bx = blockIdx.x * 16, by = blockIdx.y * 16;
    int tx = threadIdx.x, ty = threadIdx.y;
    int tid = ty * 16 + tx;

    for (int i = tid; i < 18 * 18; i += 256) {
        int r = i / 18, c = i % 18;
        sfb[r][c] = binom_at(f, by - 1 + r, bx - 1 + c);
    }
    __syncthreads();

    int y = by + ty, x = bx + tx;
    float fb = sfb[ty + 1][tx + 1];
    g_fb[y * WW + x] = fb;
    g_fq[y * WW + x] = quant(fb);
    g_gq[y * WW + x] = quant(binom_at(g, y, x));

    // central difference with replicate clamp (all clamped coords lie in the tile)
    int yp = max(y - 1, 0), yn = min(y + 1, HH - 1);
    int xp = max(x - 1, 0), xn = min(x + 1, WW - 1);
    float dfy = (sfb[yn - by + 1][tx + 1] - sfb[yp - by + 1][tx + 1]) * 0.5f;
    float dfx = (sfb[ty + 1][xn - bx + 1] - sfb[ty + 1][xp - bx + 1]) * 0.5f;
    g_dfy[y * WW + x] = dfy;
    g_dfx[y * WW + x] = dfx;
}

// ---------------- kernel 2: block matching + subpixel ----------------
__global__ __launch_bounds__(256) void match_kernel() {
    __shared__ unsigned char sf[26][28];   // fq, halo 5 (zero outside image)
    __shared__ unsigned char sg[20][20];   // gq, halo 2
    __shared__ float sdx[20][20];
    __shared__ float sdy[20][20];

    int bx = blockIdx.x * 16, by = blockIdx.y * 16;
    int tx = threadIdx.x, ty = threadIdx.y;
    int tid = ty * 16 + tx;

    for (int i = tid; i < 26 * 26; i += 256) {
        int r = i / 26, c = i % 26;
        int y = by - 5 + r, x = bx - 5 + c;
        sf[r][c] = (y >= 0 && y < HH && x >= 0 && x < WW) ? g_fq[y * WW + x] : (unsigned char)0;
    }
    for (int i = tid; i < 400; i += 256) {
        int r = i / 20, c = i % 20;
        int y = by - 2 + r, x = bx - 2 + c;
        bool in = (y >= 0 && y < HH && x >= 0 && x < WW);
        int idx = y * WW + x;
        sg[r][c]  = in ? g_gq[idx]  : (unsigned char)0;
        sdx[r][c] = in ? g_dfx[idx] : 0.0f;
        sdy[r][c] = in ? g_dfy[idx] : 0.0f;
    }
    __syncthreads();

    // cache the g patch in registers
    int gp[25];
    #pragma unroll
    for (int ky = 0; ky < 5; ky++)
        #pragma unroll
        for (int kx = 0; kx < 5; kx++)
            gp[ky * 5 + kx] = (int)sg[ty + ky][tx + kx];

    int best = 0x7fffffff, bestS = 0;
    for (int dj = -3; dj <= 3; dj++) {
        for (int di = -3; di <= 3; di++) {
            int sad = 0;
            #pragma unroll
            for (int ky = 0; ky < 5; ky++) {
                #pragma unroll
                for (int kx = 0; kx < 5; kx++) {
                    int fv = (int)sf[ty + 3 + dj + ky][tx + 3 + di + kx];
                    sad += abs(fv - gp[ky * 5 + kx]);
                }
            }
            int s = (dj + 3) * 7 + (di + 3);
            int score = sad * 64 + c_spiral[s];   // lexicographic (cost, spiral rank)
            if (score < best) { best = score; bestS = s; }
        }
    }

    int dj = bestS / 7 - 3;
    int di = bestS % 7 - 3;

    // Lucas-Kanade subpixel on the 5x5 border ring
    float a = 0.f, b = 0.f, d = 0.f, p = 0.f, q = 0.f;
    #pragma unroll
    for (int ky = 0; ky < 5; ky++) {
        #pragma unroll
        for (int kx = 0; kx < 5; kx++) {
            if (ky == 0 || ky == 4 || kx == 0 || kx == 4) {
                float dx = sdx[ty + ky][tx + kx];
                float dy = sdy[ty + ky][tx + kx];
                float fv = (float)sf[ty + 3 + dj + ky][tx + 3 + di + kx] / 255.0f;
                float gv = (float)gp[ky * 5 + kx] / 255.0f;
                float z = gv - fv;
                a += dx * dx;
                b += dx * dy;
                d += dy * dy;
                p += z * dx;
                q += z * dy;
            }
        }
    }
    // avoid FMA contraction here: det threshold must match the reference rounding
    float det = __fsub_rn(__fmul_rn(a, d), __fmul_rn(b, b));
    float u   = __fsub_rn(__fmul_rn(d, p), __fmul_rn(b, q));
    float v   = __fsub_rn(__fmul_rn(a, q), __fmul_rn(b, p));
    bool bad = (det <= 1e-7f);
    float dd = bad ? 1.0f : det;
    float sv = v / dd;   // y component
    float su = u / dd;   // x component
    if (bad || fabsf(sv) >= 1.0f) sv = 0.0f;
    if (bad || fabsf(su) >= 1.0f) su = 0.0f;

    int y = by + ty, x = bx + tx;
    g_flow1[y * WW + x]         = (float)(-dj) + sv;
    g_flow1[NPIX + y * WW + x]  = (float)(-di) + su;
}

// ---------------- kernel 3: 3x3 median (replicate padding) ----------------
__device__ __forceinline__ void mnmx(float& a, float& b) {
    float t = fminf(a, b);
    b = fmaxf(a, b);
    a = t;
}
__device__ __forceinline__ float median9(float p0, float p1, float p2,
                                         float p3, float p4, float p5,
                                         float p6, float p7, float p8) {
    mnmx(p1, p2); mnmx(p4, p5); mnmx(p7, p8);
    mnmx(p0, p1); mnmx(p3, p4); mnmx(p6, p7);
    mnmx(p1, p2); mnmx(p4, p5); mnmx(p7, p8);
    mnmx(p0, p3); mnmx(p5, p8); mnmx(p4, p7);
    mnmx(p3, p6); mnmx(p1, p4); mnmx(p2, p5);
    mnmx(p4, p7); mnmx(p4, p2); mnmx(p6, p4);
    mnmx(p4, p2);
    return p4;
}

__global__ __launch_bounds__(256) void median_kernel() {
    int x = blockIdx.x * 16 + threadIdx.x;
    int y = blockIdx.y * 16 + threadIdx.y;
    int yp = max(y - 1, 0), yn = min(y + 1, HH - 1);
    int xp = max(x - 1, 0), xn = min(x + 1, WW - 1);
    #pragma unroll
    for (int ch = 0; ch < 2; ch++) {
        const float* v = g_flow1 + ch * NPIX;
        float m = median9(v[yp * WW + xp], v[yp * WW + x], v[yp * WW + xn],
                          v[y  * WW + xp], v[y  * WW + x], v[y  * WW + xn],
                          v[yn * WW + xp], v[yn * WW + x], v[yn * WW + xn]);
        g_flow2[ch * NPIX + y * WW + x] = m;
    }
}

// ---------------- kernel 4: bilateral-style smoothing ----------------
__global__ __launch_bounds__(256) void bilateral_kernel(float* __restrict__ out) {
    const float KVAL = -1.0f / 4.5f;   // -1/(2*1.5^2)
    const float SII  = 200.0f;         //  1/(2*0.05^2)
    int x = blockIdx.x * 16 + threadIdx.x;
    int y = blockIdx.y * 16 + threadIdx.y;
    float c = g_fb[y * WW + x];
    float wsum = 0.f, s0 = 0.f, s1 = 0.f;
    #pragma unroll
    for (int dy = -2; dy <= 2; dy++) {
        #pragma unroll
        for (int dx = -2; dx <= 2; dx++) {
            int yy = y + dy, xx = x + dx;
            bool in = (yy >= 0 && yy < HH && xx >= 0 && xx < WW);
            int idx = yy * WW + xx;
            float tn = in ? g_fb[idx] : 0.0f;     // zero padding, matches reference
            float df = c - tn;
            float co = 1.0f - fabsf(KVAL - df * df * SII);
            co = fminf(fmaxf(co, 0.0f), 1.0f);
            wsum += co;                            // OOB neighbors still weigh the denom
            float v0 = in ? g_flow2[idx]        : 0.0f;
            float v1 = in ? g_flow2[NPIX + idx] : 0.0f;
            s0 += v0 * co;
            s1 += v1 * co;
        }
    }
    out[y * WW + x]        = s0 / wsum;
    out[NPIX + y * WW + x] = s1 / wsum;
}

// ---------------- launch ----------------
extern "C" void kernel_launch(void* const* d_in, const int* in_sizes, int n_in,
                              void* d_out, int out_size) {
    const float* f = (const float*)d_in[0];
    const float* g = (const float*)d_in[1];
    float* out = (float*)d_out;

    dim3 blk(16, 16);
    dim3 grd(WW / 16, HH / 16);
    prep_kernel<<<grd, blk>>>(f, g);
    match_kernel<<<grd, blk>>>();
    median_kernel<<<grd, blk>>>();
    bilateral_kernel<<<grd, blk>>>(out);
}

// round 2
// speedup vs baseline: 2.5758x; 2.5758x over previous
#include <cuda_runtime.h>
#include <stdint.h>

#define HH 256
#define WW 256
#define NPIX (HH*WW)

// ---------------- scratch (device globals; no allocations allowed) -------------
__device__ float g_fb[NPIX];        // binomial-filtered f (guide for bilateral)
__device__ float g_flow1[2*NPIX];   // vector + subpixel (before median)

// ---------------- helpers ----------------
__device__ __forceinline__ float imload(const float* __restrict__ img, int y, int x) {
    y = min(max(y, 0), HH - 1);
    x = min(max(x, 0), WW - 1);
    return __ldg(&img[y * WW + x]);
}

__device__ __forceinline__ unsigned char quant(float v) {
    float r = rintf(v * 255.0f);          // round half-to-even, matches jnp.round
    r = fminf(fmaxf(r, 0.0f), 255.0f);
    return (unsigned char)r;
}

// =================================================================
// Kernel A: binomial + quantize + gradient + block match + subpixel
// 16x16 tile per block, all intermediates in shared memory.
// =================================================================
__global__ __launch_bounds__(256) void matchA_kernel(const float* __restrict__ f,
                                                     const float* __restrict__ g) {
    // f pipeline: raw 28x28 (halo 6) -> vert 26x28 -> fb 26x26 (halo 5) -> fq u8
    __shared__ float rawf[28][28];
    __shared__ float vertf[26][28];
    __shared__ float sfb[26][26];
    __shared__ unsigned char sfq[26][32];     // 32B pitch for aligned u32 reads
    // g pipeline: raw 22x22 (halo 3) -> vert 20x22 -> gq 20x(24) (halo 2)
    __shared__ float rawg[22][22];
    __shared__ float vertg[20][22];
    __shared__ unsigned char sgq[20][24];
    __shared__ float sdx[20][20];
    __shared__ float sdy[20][20];

    const int bx = blockIdx.x * 16, by = blockIdx.y * 16;
    const int tx = threadIdx.x, ty = threadIdx.y;
    const int tid = ty * 16 + tx;

    // ---- load raw f (rows by-6..by+21, cols bx-6..bx+21), replicate clamp ----
    for (int i = tid; i < 28 * 28; i += 256) {
        int r = i / 28, c = i % 28;
        rawf[r][c] = imload(f, by - 6 + r, bx - 6 + c);
    }
    for (int i = tid; i < 22 * 22; i += 256) {
        int r = i / 22, c = i % 22;
        rawg[r][c] = imload(g, by - 3 + r, bx - 3 + c);
    }
    __syncthreads();

    // ---- vertical binomial ----
    for (int i = tid; i < 26 * 28; i += 256) {
        int r = i / 28, c = i % 28;
        vertf[r][c] = (rawf[r][c] + 2.0f * rawf[r + 1][c] + rawf[r + 2][c]) * 0.25f;
    }
    for (int i = tid; i < 20 * 22; i += 256) {
        int r = i / 22, c = i % 22;
        vertg[r][c] = (rawg[r][c] + 2.0f * rawg[r + 1][c] + rawg[r + 2][c]) * 0.25f;
    }
    __syncthreads();

    // ---- horizontal binomial + quantize (zero outside image) ----
    for (int i = tid; i < 26 * 26; i += 256) {
        int r = i / 26, c = i % 26;
        float fb = (vertf[r][c] + 2.0f * vertf[r][c + 1] + vertf[r][c + 2]) * 0.25f;
        sfb[r][c] = fb;
        int y = by - 5 + r, x = bx - 5 + c;
        bool in = (y >= 0 && y < HH && x >= 0 && x < WW);
        sfq[r][c] = in ? quant(fb) : (unsigned char)0;
    }
    // zero the pad columns of sfq (cols 26..31)
    for (int i = tid; i < 26 * 6; i += 256) {
        int r = i / 6, c = 26 + i % 6;
        sfq[r][c] = 0;
    }
    for (int i = tid; i < 20 * 20; i += 256) {
        int r = i / 20, c = i % 20;
        float gb = (vertg[r][c] + 2.0f * vertg[r][c + 1] + vertg[r][c + 2]) * 0.25f;
        int y = by - 2 + r, x = bx - 2 + c;
        bool in = (y >= 0 && y < HH && x >= 0 && x < WW);
        sgq[r][c] = in ? quant(gb) : (unsigned char)0;
    }
    __syncthreads();

    // ---- gradient of fb (replicate clamp at image border, zero outside image) ----
    for (int i = tid; i < 20 * 20; i += 256) {
        int r = i / 20, c = i % 20;
        int y = by - 2 + r, x = bx - 2 + c;
        bool in = (y >= 0 && y < HH && x >= 0 && x < WW);
        if (in) {
            int yn = min(y + 1, HH - 1) - (by - 5);
            int yp = max(y - 1, 0) - (by - 5);
            int xn = min(x + 1, WW - 1) - (bx - 5);
            int xp = max(x - 1, 0) - (bx - 5);
            sdy[r][c] = (sfb[yn][c + 3] - sfb[yp][c + 3]) * 0.5f;
            sdx[r][c] = (sfb[r + 3][xn] - sfb[r + 3][xp]) * 0.5f;
        } else {
            sdy[r][c] = 0.0f;
            sdx[r][c] = 0.0f;
        }
    }

    // write fb guide out for kernel B
    {
        int y = by + ty, x = bx + tx;
        // center pixel fb = sfb[ty+5][tx+5]; sfb already synced above
    }
    __syncthreads();
    g_fb[(by + ty) * WW + bx + tx] = sfb[ty + 5][tx + 5];

    // spiral rank of displacement s = (dj+3)*7 + (di+3)
    const int spiral[49] = {
        42,43,44,45,46,47,48,
        41,20,21,22,23,24,25,
        40,19, 6, 7, 8, 9,26,
        39,18, 5, 0, 1,10,27,
        38,17, 4, 3, 2,11,28,
        37,16,15,14,13,12,29,
        36,35,34,33,32,31,30
    };

    // ---- g template: 5 rows packed (4 bytes + 1 byte) ----
    unsigned int glo[5], ghi[5];
    #pragma unroll
    for (int ky = 0; ky < 5; ky++) {
        unsigned int b0 = sgq[ty + ky][tx + 0];
        unsigned int b1 = sgq[ty + ky][tx + 1];
        unsigned int b2 = sgq[ty + ky][tx + 2];
        unsigned int b3 = sgq[ty + ky][tx + 3];
        glo[ky] = b0 | (b1 << 8) | (b2 << 16) | (b3 << 24);
        ghi[ky] = sgq[ty + ky][tx + 4];
    }

    // ---- f neighborhood: 11 rows x 16 bytes as aligned u32 words ----
    unsigned int w0[11], w1[11], w2[11], w3[11];
    {
        int base = tx & ~3;
        #pragma unroll
        for (int r = 0; r < 11; r++) {
            const unsigned int* row = (const unsigned int*)&sfq[ty + r][base];
            w0[r] = row[0]; w1[r] = row[1]; w2[r] = row[2]; w3[r] = row[3];
        }
    }

    // ---- SAD over 7x7 displacements (SIMD), lexicographic argmin ----
    int best = 0x7fffffff;
    const int frac = tx & 3;
    #pragma unroll
    for (int dip = 0; dip < 7; dip++) {
        int o = frac + dip;
        int k = o & 3;
        unsigned int sel = 0x3210u + (unsigned)k * 0x1111u;
        unsigned int flo[11], fhi[11];
        #pragma unroll
        for (int r = 0; r < 11; r++) {
            unsigned int wA = (o < 4) ? w0[r] : ((o < 8) ? w1[r] : w2[r]);
            unsigned int wB = (o < 4) ? w1[r] : ((o < 8) ? w2[r] : w3[r]);
            flo[r] = __byte_perm(wA, wB, sel);
            fhi[r] = (wB >> (8 * k)) & 0xFFu;
        }
        #pragma unroll
        for (int djp = 0; djp < 7; djp++) {
            unsigned int sad = 0;
            #pragma unroll
            for (int ky = 0; ky < 5; ky++) {
                sad = __dp4a(__vabsdiffu4(flo[djp + ky], glo[ky]), 0x01010101u, sad);
                sad += __vabsdiffu4(fhi[djp + ky], ghi[ky]);   // only byte0 nonzero
            }
            int s = djp * 7 + dip;
            int packed = (((int)sad * 64 + spiral[s]) << 6) | s;
            best = min(best, packed);
        }
    }
    int bestS = best & 63;
    int djp = bestS / 7, dip = bestS % 7;
    int dj = djp - 3, di = dip - 3;

    // ---- Lucas-Kanade subpixel on the 5x5 border ring ----
    float a = 0.f, b = 0.f, d = 0.f, p = 0.f, q = 0.f;
    #pragma unroll
    for (int ky = 0; ky < 5; ky++) {
        #pragma unroll
        for (int kx = 0; kx < 5; kx++) {
            if (ky == 0 || ky == 4 || kx == 0 || kx == 4) {
                float dx = sdx[ty + ky][tx + kx];
                float dy = sdy[ty + ky][tx + kx];
                float fv = (float)sfq[ty + djp + ky][tx + dip + kx] * (1.0f / 255.0f);
                unsigned int gb = (kx < 4) ? ((glo[ky] >> (8 * kx)) & 0xFFu) : ghi[ky];
                float gv = (float)gb * (1.0f / 255.0f);
                float z = gv - fv;
                a += dx * dx;
                b += dx * dy;
                d += dy * dy;
                p += z * dx;
                q += z * dy;
            }
        }
    }
    // avoid FMA contraction: det threshold must match the reference rounding
    float det = __fsub_rn(__fmul_rn(a, d), __fmul_rn(b, b));
    float u   = __fsub_rn(__fmul_rn(d, p), __fmul_rn(b, q));
    float v   = __fsub_rn(__fmul_rn(a, q), __fmul_rn(b, p));
    bool bad = (det <= 1e-7f);
    float dd = bad ? 1.0f : det;
    float sv = v / dd;   // y component
    float su = u / dd;   // x component
    if (bad || fabsf(sv) >= 1.0f) sv = 0.0f;
    if (bad || fabsf(su) >= 1.0f) su = 0.0f;

    int y = by + ty, x = bx + tx;
    g_flow1[y * WW + x]        = (float)(-dj) + sv;
    g_flow1[NPIX + y * WW + x] = (float)(-di) + su;
}

// =================================================================
// Kernel B: 3x3 median (replicate) + bilateral smoothing (zero pad)
// =================================================================
__device__ __forceinline__ void mnmx(float& a, float& b) {
    float t = fminf(a, b);
    b = fmaxf(a, b);
    a = t;
}
__device__ __forceinline__ float median9(float p0, float p1, float p2,
                                         float p3, float p4, float p5,
                                         float p6, float p7, float p8) {
    mnmx(p1, p2); mnmx(p4, p5); mnmx(p7, p8);
    mnmx(p0, p1); mnmx(p3, p4); mnmx(p6, p7);
    mnmx(p1, p2); mnmx(p4, p5); mnmx(p7, p8);
    mnmx(p0, p3); mnmx(p5, p8); mnmx(p4, p7);
    mnmx(p3, p6); mnmx(p1, p4); mnmx(p2, p5);
    mnmx(p4, p7); mnmx(p4, p2); mnmx(p6, p4);
    mnmx(p4, p2);
    return p4;
}

__global__ __launch_bounds__(256) void smoothB_kernel(float* __restrict__ out) {
    __shared__ float sflow0[22][22];   // flow1 ch0, halo 3, replicate clamp
    __shared__ float sflow1[22][22];
    __shared__ float smed0[20][20];    // median flow, halo 2, zero outside image
    __shared__ float smed1[20][20];
    __shared__ float sguide[20][20];   // fb guide, halo 2, zero outside image

    const int bx = blockIdx.x * 16, by = blockIdx.y * 16;
    const int tx = threadIdx.x, ty = threadIdx.y;
    const int tid = ty * 16 + tx;

    for (int i = tid; i < 22 * 22; i += 256) {
        int r = i / 22, c = i % 22;
        int y = min(max(by - 3 + r, 0), HH - 1);
        int x = min(max(bx - 3 + c, 0), WW - 1);
        sflow0[r][c] = g_flow1[y * WW + x];
        sflow1[r][c] = g_flow1[NPIX + y * WW + x];
    }
    __syncthreads();

    for (int i = tid; i < 20 * 20; i += 256) {
        int r = i / 20, c = i % 20;
        int y = by - 2 + r, x = bx - 2 + c;
        bool in = (y >= 0 && y < HH && x >= 0 && x < WW);
        float m0 = 0.0f, m1 = 0.0f, gd = 0.0f;
        if (in) {
            m0 = median9(sflow0[r][c],   sflow0[r][c+1],   sflow0[r][c+2],
                         sflow0[r+1][c], sflow0[r+1][c+1], sflow0[r+1][c+2],
                         sflow0[r+2][c], sflow0[r+2][c+1], sflow0[r+2][c+2]);
            m1 = median9(sflow1[r][c],   sflow1[r][c+1],   sflow1[r][c+2],
                         sflow1[r+1][c], sflow1[r+1][c+1], sflow1[r+1][c+2],
                         sflow1[r+2][c], sflow1[r+2][c+1], sflow1[r+2][c+2]);
            gd = g_fb[y * WW + x];
        }
        smed0[r][c] = m0;
        smed1[r][c] = m1;
        sguide[r][c] = gd;
    }
    __syncthreads();

    const float KVAL = -1.0f / 4.5f;   // -1/(2*1.5^2)
    const float SII  = 200.0f;         //  1/(2*0.05^2)
    float c = sguide[ty + 2][tx + 2];
    float wsum = 0.f, s0 = 0.f, s1 = 0.f;
    #pragma unroll
    for (int dy = 0; dy < 5; dy++) {
        #pragma unroll
        for (int dx = 0; dx < 5; dx++) {
            float tn = sguide[ty + dy][tx + dx];   // zero outside image (matches ref)
            float df = c - tn;
            float co = 1.0f - fabsf(KVAL - df * df * SII);
            co = fminf(fmaxf(co, 0.0f), 1.0f);
            wsum += co;                             // OOB neighbors still weigh denom
            s0 += smed0[ty + dy][tx + dx] * co;
            s1 += smed1[ty + dy][tx + dx] * co;
        }
    }
    int y = by + ty, x = bx + tx;
    out[y * WW + x]        = s0 / wsum;
    out[NPIX + y * WW + x] = s1 / wsum;
}

// ---------------- launch ----------------
extern "C" void kernel_launch(void* const* d_in, const int* in_sizes, int n_in,
                              void* d_out, int out_size) {
    const float* f = (const float*)d_in[0];
    const float* g = (const float*)d_in[1];
    float* out = (float*)d_out;

    dim3 blk(16, 16);
    dim3 grd(WW / 16, HH / 16);
    matchA_kernel<<<grd, blk>>>(f, g);
    smoothB_kernel<<<grd, blk>>>(out);
}